// round 2
// baseline (speedup 1.0000x reference)
#include <cuda_runtime.h>
#include <cuda_bf16.h>

#define TT 1024
#define BB 4096
#define CHUNKS 128
#define ROWS_PER (BB / CHUNKS)      // 32
#define TGROUPS (TT / 256)          // 4
#define NEGBIG (-1.0e30f)

// ---- device scratch (statically allocated; counters self-reset each launch) ----
__device__ __align__(16) float g_S[TT * 3 * CHUNKS];   // per (t,c,chunk) kl partial sums
__device__ __align__(16) int   g_C[TT * 3 * CHUNKS];   // per (t,c,chunk) counts
__device__ float        g_gloss[TGROUPS];
__device__ unsigned int g_cnt1[TGROUPS];
__device__ unsigned int g_cnt2;

// ======================= special functions =======================
// Stirling lgamma for y >= 5  (abs err < 3e-7)
__device__ __forceinline__ float stirl_lg(float y) {
    float r  = __fdividef(1.0f, y);
    float L  = __logf(y);
    float r2 = r * r;
    return fmaf(y - 0.5f, L,
                fmaf(r, fmaf(r2, -2.7777778e-3f, 8.3333333e-2f), 0.91893853f - y));
}

// Stirling lgamma + digamma for y >= 5
__device__ __forceinline__ void stirl_both(float y, float& lg, float& ps) {
    float r  = __fdividef(1.0f, y);
    float L  = __logf(y);
    float r2 = r * r;
    lg = fmaf(y - 0.5f, L,
              fmaf(r, fmaf(r2, -2.7777778e-3f, 8.3333333e-2f), 0.91893853f - y));
    // psi(y) = L - r/2 - r2*(1/12 - r2/120)
    ps = fmaf(-r2, fmaf(-r2, 8.3333333e-3f, 8.3333333e-2f), fmaf(-0.5f, r, L));
}

// KL( Beta(ta,tb) || Beta(pa,pb) ), sp = tc+2, sq = pc+2 identities.
__device__ __forceinline__ float elem_kl(float l0, float l1, float tw, float tcv) {
    float pw  = __fdividef(1.0f, 1.0f + __expf(-l0));
    float pcs = __fdividef(1.0f, 1.0f + __expf(-l1));
    float pc  = fmaf(pcs, 1023.0f, 5.0f);          // (T-1) = 1023

    float sp = tcv + 2.0f;                          // = ta + tb exactly
    float sq = pc + 2.0f;                           // = pa + pb exactly
    float ta = fmaf(tcv, tw, 1.0f);
    float tb = sp - ta;
    float pa = fmaf(pc, pw, 1.0f);
    float pb = sq - pa;

    // shift-by-4 products: P(x) = x(x+1)(x+2)(x+3) = u(u+2), u = x(x+3)
    float uta = ta * (ta + 3.0f), Pta = uta * (uta + 2.0f);
    float utb = tb * (tb + 3.0f), Ptb = utb * (utb + 2.0f);
    float upa = pa * (pa + 3.0f), Ppa = upa * (upa + 2.0f);
    float upb = pb * (pb + 3.0f), Ppb = upb * (upb + 2.0f);

    float lgta, psta; stirl_both(ta + 4.0f, lgta, psta);
    float lgtb, pstb; stirl_both(tb + 4.0f, lgtb, pstb);
    float lgsp, pssp; stirl_both(sp,        lgsp, pssp);   // sp in [7,32]
    float lgpa = stirl_lg(pa + 4.0f);
    float lgpb = stirl_lg(pb + 4.0f);
    float lgsq = stirl_lg(sq);                             // sq in (7,1030)

    float da = ta - pa, db = tb - pb;
    // psi shift corrections via common denominator (single divide):
    // da*P'ta/Pta + db*P'tb/Ptb = (da*P'ta*Ptb + db*P'tb*Pta) / (Pta*Ptb)
    float Aa  = fmaf(2.0f, uta, 2.0f) * fmaf(2.0f, ta, 3.0f);
    float Ab  = fmaf(2.0f, utb, 2.0f) * fmaf(2.0f, tb, 3.0f);
    float Ptt = Pta * Ptb;
    float corr = __fdividef(fmaf(da * Aa, Ptb, db * Ab * Pta), Ptt);

    float logdiff = __logf(Ptt) - __logf(Ppa * Ppb);

    return (lgpa + lgpb + lgsp) - (lgta + lgtb + lgsq) + logdiff
         + da * psta + db * pstb + (sq - sp) * pssp - corr;
}

// ======================= single fused kernel =======================
// grid: (CHUNKS, TGROUPS), block: 256 threads; thread owns one t, loops 32 b-rows.
__global__ void __launch_bounds__(256)
fused_kernel(const float* __restrict__ logits, const float* __restrict__ tgt,
             float* __restrict__ out) {
    const int tid = threadIdx.x;
    const int ch  = blockIdx.x;        // b-chunk
    const int tg  = blockIdx.y;        // t-group
    const int t   = tg * 256 + tid;

    float a0 = 0.0f, a1 = 0.0f, a2 = 0.0f;
    int   n0 = 0, n1 = 0, n2 = 0;
    const int b0 = ch * ROWS_PER;

#pragma unroll 4
    for (int i = 0; i < ROWS_PER; i++) {
        size_t e = (size_t)(b0 + i) * TT + t;
        const float* tp = tgt + e * 3;
        float x0 = __ldg(tp);
        float x1 = __ldg(tp + 1);
        float x2 = __ldg(tp + 2);
        float2 lv = *reinterpret_cast<const float2*>(logits + e * 2);

        bool  m  = (x2 > NEGBIG);             // padded rows are -inf in all 3
        float tw = m ? x0 : 0.5f;
        float tc = m ? x1 : 5.0f;
        float kl = elem_kl(lv.x, lv.y, tw, tc);
        int   dx = m ? (int)x2 : -1;

        a0 += (dx == 0) ? kl : 0.0f;  n0 += (dx == 0);
        a1 += (dx == 1) ? kl : 0.0f;  n1 += (dx == 1);
        a2 += (dx == 2) ? kl : 0.0f;  n2 += (dx == 2);
    }

    // deterministic slab write: layout [t][c][chunk]
    {
        int base = (t * 3) * CHUNKS + ch;
        g_S[base]              = a0;
        g_S[base + CHUNKS]     = a1;
        g_S[base + 2 * CHUNKS] = a2;
        g_C[base]              = n0;
        g_C[base + CHUNKS]     = n1;
        g_C[base + 2 * CHUNKS] = n2;
    }
    __threadfence();
    __syncthreads();

    __shared__ bool amLast;
    if (tid == 0)
        amLast = (atomicAdd(&g_cnt1[tg], 1u) == (unsigned)(CHUNKS - 1));
    __syncthreads();
    if (!amLast) return;
    __threadfence();

    // last block of this t-group: reduce its 256 t's over all chunks (fixed order)
    float term = 0.0f;
#pragma unroll
    for (int c = 0; c < 3; c++) {
        const float4* ps = reinterpret_cast<const float4*>(&g_S[(t * 3 + c) * CHUNKS]);
        const int4*   pn = reinterpret_cast<const int4*>(&g_C[(t * 3 + c) * CHUNKS]);
        float s = 0.0f; int n = 0;
#pragma unroll
        for (int k = 0; k < CHUNKS / 4; k++) {
            float4 v = ps[k]; s += (v.x + v.y) + (v.z + v.w);
            int4   w = pn[k]; n += (w.x + w.y) + (w.z + w.w);
        }
        term += (n > 0) ? s / (3.0f * (float)n) : 0.0f;
    }

    // block reduce 256 per-t terms (fixed order)
#pragma unroll
    for (int off = 16; off > 0; off >>= 1)
        term += __shfl_xor_sync(0xffffffffu, term, off);
    __shared__ float ws[8];
    if ((tid & 31) == 0) ws[tid >> 5] = term;
    __syncthreads();

    if (tid == 0) {
        float s = 0.0f;
#pragma unroll
        for (int i = 0; i < 8; i++) s += ws[i];
        g_gloss[tg] = s;
        g_cnt1[tg]  = 0;                       // reset for next graph replay
        __threadfence();
        if (atomicAdd(&g_cnt2, 1u) == (unsigned)(TGROUPS - 1)) {
            __threadfence();
            float tot = 0.0f;
#pragma unroll
            for (int i = 0; i < TGROUPS; i++) tot += g_gloss[i];
            out[0] = tot * (1.0f / (float)TT);
            g_cnt2 = 0;                        // reset for next graph replay
        }
    }
}

// ======================= launch =======================
extern "C" void kernel_launch(void* const* d_in, const int* in_sizes, int n_in,
                              void* d_out, int out_size) {
    const float* logits;
    const float* targets;
    if (in_sizes[0] == BB * TT * 2) {          // robust to metadata ordering
        logits  = (const float*)d_in[0];
        targets = (const float*)d_in[1];
    } else {
        logits  = (const float*)d_in[1];
        targets = (const float*)d_in[0];
    }
    float* out = (float*)d_out;

    fused_kernel<<<dim3(CHUNKS, TGROUPS), 256>>>(logits, targets, out);
}

// round 3
// speedup vs baseline: 2.0419x; 2.0419x over previous
#include <cuda_runtime.h>
#include <cuda_bf16.h>

#define TT 1024
#define BB 4096
#define TOTAL4 (BB * TT / 4)        // 1048576 float4-groups
#define NBLK 592                    // 4 * 148 SMs -> exactly 4 blocks/SM
#define RCHUNK 8                    // blk-dim chunks in reducer
#define RBLKS (12 * RCHUNK)         // 96 reducer blocks
#define PER_CHUNK (NBLK / RCHUNK)   // 74
#define NEGBIG (-1.0e30f)

// ---- device scratch (static; counters self-reset each launch) ----
__device__ __align__(16) float        g_S[NBLK * 3072];    // [blk][3t+c] kl sums
__device__ __align__(16) unsigned int g_Cn[NBLK * 768];    // [blk][3*(t>>2)+c] byte(t&3)
__device__ __align__(16) float        g_pS[RCHUNK * 3072]; // reducer partials
__device__ __align__(16) int          g_pN[RCHUNK * 3072];
__device__ unsigned int g_rcnt;

// ======================= special functions =======================
// Stirling lgamma for y >= 5  (abs err < 3e-7)
__device__ __forceinline__ float stirl_lg(float y) {
    float r  = __fdividef(1.0f, y);
    float L  = __logf(y);
    float r2 = r * r;
    return fmaf(y - 0.5f, L,
                fmaf(r, fmaf(r2, -2.7777778e-3f, 8.3333333e-2f), 0.91893853f - y));
}

// Stirling lgamma + digamma for y >= 5
__device__ __forceinline__ void stirl_both(float y, float& lg, float& ps) {
    float r  = __fdividef(1.0f, y);
    float L  = __logf(y);
    float r2 = r * r;
    lg = fmaf(y - 0.5f, L,
              fmaf(r, fmaf(r2, -2.7777778e-3f, 8.3333333e-2f), 0.91893853f - y));
    ps = fmaf(-r2, fmaf(-r2, 8.3333333e-3f, 8.3333333e-2f), fmaf(-0.5f, r, L));
}

// KL( Beta(ta,tb) || Beta(pa,pb) ), sp = tc+2, sq = pc+2 identities.
__device__ __forceinline__ float elem_kl(float l0, float l1, float tw, float tcv) {
    float pw  = __fdividef(1.0f, 1.0f + __expf(-l0));
    float pcs = __fdividef(1.0f, 1.0f + __expf(-l1));
    float pc  = fmaf(pcs, 1023.0f, 5.0f);

    float sp = tcv + 2.0f;
    float sq = pc + 2.0f;
    float ta = fmaf(tcv, tw, 1.0f);
    float tb = sp - ta;
    float pa = fmaf(pc, pw, 1.0f);
    float pb = sq - pa;

    float uta = ta * (ta + 3.0f), Pta = uta * (uta + 2.0f);
    float utb = tb * (tb + 3.0f), Ptb = utb * (utb + 2.0f);
    float upa = pa * (pa + 3.0f), Ppa = upa * (upa + 2.0f);
    float upb = pb * (pb + 3.0f), Ppb = upb * (upb + 2.0f);

    float lgta, psta; stirl_both(ta + 4.0f, lgta, psta);
    float lgtb, pstb; stirl_both(tb + 4.0f, lgtb, pstb);
    float lgsp, pssp; stirl_both(sp,        lgsp, pssp);
    float lgpa = stirl_lg(pa + 4.0f);
    float lgpb = stirl_lg(pb + 4.0f);
    float lgsq = stirl_lg(sq);

    float da = ta - pa, db = tb - pb;
    float Aa  = fmaf(2.0f, uta, 2.0f) * fmaf(2.0f, ta, 3.0f);
    float Ab  = fmaf(2.0f, utb, 2.0f) * fmaf(2.0f, tb, 3.0f);
    float Ptt = Pta * Ptb;
    float corr = __fdividef(fmaf(da * Aa, Ptb, db * Ab * Pta), Ptt);

    float logdiff = __logf(Ptt) - __logf(Ppa * Ppb);

    return (lgpa + lgpb + lgsp) - (lgta + lgtb + lgsq) + logdiff
         + da * psta + db * pstb + (sq - sp) * pssp - corr;
}

// ======================= kernel 1: main KL pass =======================
// 592 blocks x 256 threads; thread owns t = 4*tid+j (fixed across grid-stride).
__global__ void __launch_bounds__(256)
main_kernel(const float* __restrict__ logits, const float* __restrict__ tgt) {
    const int tid = threadIdx.x;
    const float4* tg4 = reinterpret_cast<const float4*>(tgt);
    const float4* lg4 = reinterpret_cast<const float4*>(logits);

    float s[4][3];
#pragma unroll
    for (int j = 0; j < 4; j++) { s[j][0] = 0.0f; s[j][1] = 0.0f; s[j][2] = 0.0f; }
    unsigned int cn0 = 0, cn1 = 0, cn2 = 0;   // byte j of cn_c = count of class c at t=4tid+j

#pragma unroll 1
    for (int g = blockIdx.x * 256 + tid; g < TOTAL4; g += NBLK * 256) {
        float4 a = tg4[g * 3 + 0];
        float4 b = tg4[g * 3 + 1];
        float4 c = tg4[g * 3 + 2];
        float4 d = lg4[g * 2 + 0];
        float4 e = lg4[g * 2 + 1];
        float tv[12] = {a.x, a.y, a.z, a.w, b.x, b.y, b.z, b.w, c.x, c.y, c.z, c.w};
        float lv[8]  = {d.x, d.y, d.z, d.w, e.x, e.y, e.z, e.w};
#pragma unroll
        for (int j = 0; j < 4; j++) {
            float x0 = tv[3 * j], x1 = tv[3 * j + 1], x2 = tv[3 * j + 2];
            bool  m  = (x2 > NEGBIG);
            float tw = m ? x0 : 0.5f;
            float tc = m ? x1 : 5.0f;
            int   dx = m ? (int)x2 : -1;
            float kl = elem_kl(lv[2 * j], lv[2 * j + 1], tw, tc);
            s[j][0] += (dx == 0) ? kl : 0.0f;
            s[j][1] += (dx == 1) ? kl : 0.0f;
            s[j][2] += (dx == 2) ? kl : 0.0f;
            cn0 += (dx == 0) ? (1u << (8 * j)) : 0u;
            cn1 += (dx == 1) ? (1u << (8 * j)) : 0u;
            cn2 += (dx == 2) ? (1u << (8 * j)) : 0u;
        }
    }

    // coalesced slab write: [blk][12*tid + 3j + c] == [blk][3t + c]
    float4* so = reinterpret_cast<float4*>(&g_S[blockIdx.x * 3072 + 12 * tid]);
    so[0] = make_float4(s[0][0], s[0][1], s[0][2], s[1][0]);
    so[1] = make_float4(s[1][1], s[1][2], s[2][0], s[2][1]);
    so[2] = make_float4(s[2][2], s[3][0], s[3][1], s[3][2]);
    unsigned int* co = &g_Cn[blockIdx.x * 768 + 3 * tid];
    co[0] = cn0; co[1] = cn1; co[2] = cn2;
}

// ======================= kernel 2: reduce + finalize =======================
// grid RBLKS=96: i = tc-chunk (0..11), k = blk-chunk (0..7). Last block folds.
__global__ void __launch_bounds__(256)
reduce_kernel(float* __restrict__ out) {
    const int tid = threadIdx.x;
    const int i = blockIdx.x / RCHUNK;     // tc chunk
    const int k = blockIdx.x % RCHUNK;     // blk chunk
    const int p = i * 256 + tid;           // pair index = 3t+c
    const int t = p / 3, c = p - 3 * t;
    const int wIdx = 3 * (t >> 2) + c;
    const int sh   = 8 * (t & 3);

    float sS = 0.0f; int sN = 0;
    const int b0 = k * PER_CHUNK;
#pragma unroll 2
    for (int b = b0; b < b0 + PER_CHUNK; b++) {
        sS += g_S[b * 3072 + p];
        sN += (int)((g_Cn[b * 768 + wIdx] >> sh) & 0xFFu);
    }
    g_pS[k * 3072 + p] = sS;
    g_pN[k * 3072 + p] = sN;
    __threadfence();
    __syncthreads();

    __shared__ bool amLast;
    if (tid == 0)
        amLast = (atomicAdd(&g_rcnt, 1u) == (unsigned)(RBLKS - 1));
    __syncthreads();
    if (!amLast) return;
    __threadfence();

    // fold: thread handles t = 4*tid + j
    float acc = 0.0f;
#pragma unroll
    for (int j = 0; j < 4; j++) {
        int tt = 4 * tid + j;
#pragma unroll
        for (int cc = 0; cc < 3; cc++) {
            int pp = 3 * tt + cc;
            float S = 0.0f; int N = 0;
#pragma unroll
            for (int kk = 0; kk < RCHUNK; kk++) {
                S += g_pS[kk * 3072 + pp];
                N += g_pN[kk * 3072 + pp];
            }
            acc += (N > 0) ? __fdividef(S, 3.0f * (float)N) : 0.0f;
        }
    }

#pragma unroll
    for (int off = 16; off > 0; off >>= 1)
        acc += __shfl_xor_sync(0xffffffffu, acc, off);
    __shared__ float ws[8];
    if ((tid & 31) == 0) ws[tid >> 5] = acc;
    __syncthreads();
    if (tid == 0) {
        float tot = 0.0f;
#pragma unroll
        for (int w = 0; w < 8; w++) tot += ws[w];
        out[0] = tot * (1.0f / (float)TT);
        g_rcnt = 0;                          // reset for next graph replay
    }
}

// ======================= launch =======================
extern "C" void kernel_launch(void* const* d_in, const int* in_sizes, int n_in,
                              void* d_out, int out_size) {
    const float* logits;
    const float* targets;
    if (in_sizes[0] == BB * TT * 2) {          // robust to metadata ordering
        logits  = (const float*)d_in[0];
        targets = (const float*)d_in[1];
    } else {
        logits  = (const float*)d_in[1];
        targets = (const float*)d_in[0];
    }
    float* out = (float*)d_out;

    main_kernel<<<NBLK, 256>>>(logits, targets);
    reduce_kernel<<<RBLKS, 256>>>(out);
}

// round 4
// speedup vs baseline: 2.3028x; 1.1278x over previous
#include <cuda_runtime.h>
#include <cuda_bf16.h>

#define TT 1024
#define BB 4096
#define TOTAL4 (BB * TT / 4)        // 1048576 float4-groups
#define NBLK 592                    // 4 * 148 SMs
#define QN 148                      // NBLK / 4 quarters
#define RBLKS 60                    // 48 S-blocks + 12 count-blocks
#define NEGBIG (-1.0e30f)

// ---- device scratch (static; counter self-resets each launch) ----
__device__ __align__(16) float        g_St[3072 * NBLK];  // [p=3t+c][blk]
__device__ __align__(16) unsigned int g_Ct[768 * NBLK];   // [pc=3*(t>>2)+c][blk], byte=t&3
__device__ __align__(16) float        g_pS[3072];
__device__ __align__(16) int          g_pN[3072];
__device__ unsigned int g_rcnt;

// ======================= special functions =======================
__device__ __forceinline__ float stirl_lg(float y) {
    float r  = __fdividef(1.0f, y);
    float L  = __logf(y);
    float r2 = r * r;
    return fmaf(y - 0.5f, L,
                fmaf(r, fmaf(r2, -2.7777778e-3f, 8.3333333e-2f), 0.91893853f - y));
}

__device__ __forceinline__ void stirl_both(float y, float& lg, float& ps) {
    float r  = __fdividef(1.0f, y);
    float L  = __logf(y);
    float r2 = r * r;
    lg = fmaf(y - 0.5f, L,
              fmaf(r, fmaf(r2, -2.7777778e-3f, 8.3333333e-2f), 0.91893853f - y));
    ps = fmaf(-r2, fmaf(-r2, 8.3333333e-3f, 8.3333333e-2f), fmaf(-0.5f, r, L));
}

__device__ __forceinline__ float elem_kl(float l0, float l1, float tw, float tcv) {
    float pw  = __fdividef(1.0f, 1.0f + __expf(-l0));
    float pcs = __fdividef(1.0f, 1.0f + __expf(-l1));
    float pc  = fmaf(pcs, 1023.0f, 5.0f);

    float sp = tcv + 2.0f;
    float sq = pc + 2.0f;
    float ta = fmaf(tcv, tw, 1.0f);
    float tb = sp - ta;
    float pa = fmaf(pc, pw, 1.0f);
    float pb = sq - pa;

    float uta = ta * (ta + 3.0f), Pta = uta * (uta + 2.0f);
    float utb = tb * (tb + 3.0f), Ptb = utb * (utb + 2.0f);
    float upa = pa * (pa + 3.0f), Ppa = upa * (upa + 2.0f);
    float upb = pb * (pb + 3.0f), Ppb = upb * (upb + 2.0f);

    float lgta, psta; stirl_both(ta + 4.0f, lgta, psta);
    float lgtb, pstb; stirl_both(tb + 4.0f, lgtb, pstb);
    float lgsp, pssp; stirl_both(sp,        lgsp, pssp);
    float lgpa = stirl_lg(pa + 4.0f);
    float lgpb = stirl_lg(pb + 4.0f);
    float lgsq = stirl_lg(sq);

    float da = ta - pa, db = tb - pb;
    float Aa  = fmaf(2.0f, uta, 2.0f) * fmaf(2.0f, ta, 3.0f);
    float Ab  = fmaf(2.0f, utb, 2.0f) * fmaf(2.0f, tb, 3.0f);
    float Ptt = Pta * Ptb;
    float corr = __fdividef(fmaf(da * Aa, Ptb, db * Ab * Pta), Ptt);

    float logdiff = __logf(Ptt) - __logf(Ppa * Ppb);

    return (lgpa + lgpb + lgsp) - (lgta + lgtb + lgsq) + logdiff
         + da * psta + db * pstb + (sq - sp) * pssp - corr;
}

// ======================= kernel 1: main KL pass =======================
__global__ void __launch_bounds__(256)
main_kernel(const float* __restrict__ logits, const float* __restrict__ tgt) {
    const int tid = threadIdx.x;
    const float4* tg4 = reinterpret_cast<const float4*>(tgt);
    const float4* lg4 = reinterpret_cast<const float4*>(logits);

    float s[4][3];
#pragma unroll
    for (int j = 0; j < 4; j++) { s[j][0] = 0.0f; s[j][1] = 0.0f; s[j][2] = 0.0f; }
    unsigned int cn0 = 0, cn1 = 0, cn2 = 0;

#pragma unroll 1
    for (int g = blockIdx.x * 256 + tid; g < TOTAL4; g += NBLK * 256) {
        float4 a = tg4[g * 3 + 0];
        float4 b = tg4[g * 3 + 1];
        float4 c = tg4[g * 3 + 2];
        float4 d = lg4[g * 2 + 0];
        float4 e = lg4[g * 2 + 1];
        float tv[12] = {a.x, a.y, a.z, a.w, b.x, b.y, b.z, b.w, c.x, c.y, c.z, c.w};
        float lv[8]  = {d.x, d.y, d.z, d.w, e.x, e.y, e.z, e.w};
#pragma unroll
        for (int j = 0; j < 4; j++) {
            float x0 = tv[3 * j], x1 = tv[3 * j + 1], x2 = tv[3 * j + 2];
            bool  m  = (x2 > NEGBIG);
            float tw = m ? x0 : 0.5f;
            float tc = m ? x1 : 5.0f;
            int   dx = m ? (int)x2 : -1;
            float kl = elem_kl(lv[2 * j], lv[2 * j + 1], tw, tc);
            s[j][0] += (dx == 0) ? kl : 0.0f;
            s[j][1] += (dx == 1) ? kl : 0.0f;
            s[j][2] += (dx == 2) ? kl : 0.0f;
            cn0 += (dx == 0) ? (1u << (8 * j)) : 0u;
            cn1 += (dx == 1) ? (1u << (8 * j)) : 0u;
            cn2 += (dx == 2) ? (1u << (8 * j)) : 0u;
        }
    }

    // transposed slab write: g_St[p][blk], p = 3t+c = 12*tid+3j+c
    const int blk = blockIdx.x;
#pragma unroll
    for (int j = 0; j < 4; j++)
#pragma unroll
        for (int c = 0; c < 3; c++)
            g_St[(12 * tid + 3 * j + c) * NBLK + blk] = s[j][c];
    g_Ct[(3 * tid + 0) * NBLK + blk] = cn0;
    g_Ct[(3 * tid + 1) * NBLK + blk] = cn1;
    g_Ct[(3 * tid + 2) * NBLK + blk] = cn2;
}

// ======================= kernel 2: reduce + finalize =======================
// blocks 0..47: S sums (4 threads per p). blocks 48..59: count sums (4 per pc).
__global__ void __launch_bounds__(256)
reduce_kernel(float* __restrict__ out) {
    const int tid = threadIdx.x;

    if (blockIdx.x < 48) {
        int q = blockIdx.x * 256 + tid;
        int p = q >> 2, quar = q & 3;
        const float4* src = reinterpret_cast<const float4*>(&g_St[p * NBLK + quar * QN]);
        float ssum = 0.0f;
#pragma unroll
        for (int k = 0; k < QN / 4; k++) {
            float4 v = src[k];
            ssum += (v.x + v.y) + (v.z + v.w);
        }
        ssum += __shfl_down_sync(0xffffffffu, ssum, 1);
        ssum += __shfl_down_sync(0xffffffffu, ssum, 2);
        if (quar == 0) g_pS[p] = ssum;
    } else {
        int q = (blockIdx.x - 48) * 256 + tid;          // 0..3071
        int pc = q >> 2, quar = q & 3;
        const uint4* src = reinterpret_cast<const uint4*>(&g_Ct[pc * NBLK + quar * QN]);
        int n0 = 0, n1 = 0, n2 = 0, n3 = 0;
        int k = 0;
#pragma unroll
        for (int chunk = 0; chunk < 5; chunk++) {       // 37 uint4 = 8+8+8+8+5
            unsigned int acc = 0;
            int lim = (chunk < 4) ? (k + 8) : 37;       // <=32 packed words/chunk: no carry
#pragma unroll
            for (; k < lim; k++) {
                uint4 v = src[k];
                acc += v.x + v.y + v.z + v.w;
            }
            n0 += (int)(acc & 0xFFu);
            n1 += (int)((acc >> 8) & 0xFFu);
            n2 += (int)((acc >> 16) & 0xFFu);
            n3 += (int)((acc >> 24) & 0xFFu);
        }
        n0 += __shfl_down_sync(0xffffffffu, n0, 1); n0 += __shfl_down_sync(0xffffffffu, n0, 2);
        n1 += __shfl_down_sync(0xffffffffu, n1, 1); n1 += __shfl_down_sync(0xffffffffu, n1, 2);
        n2 += __shfl_down_sync(0xffffffffu, n2, 1); n2 += __shfl_down_sync(0xffffffffu, n2, 2);
        n3 += __shfl_down_sync(0xffffffffu, n3, 1); n3 += __shfl_down_sync(0xffffffffu, n3, 2);
        if (quar == 0) {
            int t4 = pc / 3, cc = pc - 3 * t4;          // t = 4*t4 + j
            g_pN[12 * t4 + 0 + cc] = n0;
            g_pN[12 * t4 + 3 + cc] = n1;
            g_pN[12 * t4 + 6 + cc] = n2;
            g_pN[12 * t4 + 9 + cc] = n3;
        }
    }

    __threadfence();
    __syncthreads();
    __shared__ bool amLast;
    if (tid == 0)
        amLast = (atomicAdd(&g_rcnt, 1u) == (unsigned)(RBLKS - 1));
    __syncthreads();
    if (!amLast) return;
    __threadfence();

    // fold: thread owns t = 4*tid+j; read 12 S + 12 N (contiguous, vectorized)
    const float4* ps4 = reinterpret_cast<const float4*>(&g_pS[12 * tid]);
    const int4*   pn4 = reinterpret_cast<const int4*>(&g_pN[12 * tid]);
    float acc = 0.0f;
#pragma unroll
    for (int k = 0; k < 3; k++) {
        float4 S = ps4[k];
        int4   N = pn4[k];
        acc += (N.x > 0) ? __fdividef(S.x, 3.0f * (float)N.x) : 0.0f;
        acc += (N.y > 0) ? __fdividef(S.y, 3.0f * (float)N.y) : 0.0f;
        acc += (N.z > 0) ? __fdividef(S.z, 3.0f * (float)N.z) : 0.0f;
        acc += (N.w > 0) ? __fdividef(S.w, 3.0f * (float)N.w) : 0.0f;
    }

#pragma unroll
    for (int off = 16; off > 0; off >>= 1)
        acc += __shfl_xor_sync(0xffffffffu, acc, off);
    __shared__ float ws[8];
    if ((tid & 31) == 0) ws[tid >> 5] = acc;
    __syncthreads();
    if (tid == 0) {
        float tot = 0.0f;
#pragma unroll
        for (int w = 0; w < 8; w++) tot += ws[w];
        out[0] = tot * (1.0f / (float)TT);
        g_rcnt = 0;                                     // reset for next replay
    }
}

// ======================= launch =======================
extern "C" void kernel_launch(void* const* d_in, const int* in_sizes, int n_in,
                              void* d_out, int out_size) {
    const float* logits;
    const float* targets;
    if (in_sizes[0] == BB * TT * 2) {
        logits  = (const float*)d_in[0];
        targets = (const float*)d_in[1];
    } else {
        logits  = (const float*)d_in[1];
        targets = (const float*)d_in[0];
    }
    float* out = (float*)d_out;

    main_kernel<<<NBLK, 256>>>(logits, targets);
    reduce_kernel<<<RBLKS, 256>>>(out);
}

// round 5
// speedup vs baseline: 2.5586x; 1.1111x over previous
#include <cuda_runtime.h>
#include <cuda_bf16.h>

#define TT 1024
#define BB 4096
#define TOTAL4 (BB * TT / 4)        // 1048576 float4-groups
#define NBLK 592                    // 4 * 148 SMs
#define BSPLIT 8
#define PER (NBLK / BSPLIT)         // 74
#define RBLKS 120                   // 96 S-blocks + 24 count-blocks
#define NEGBIG (-1.0e30f)

// ---- device scratch (static; counter self-resets each launch) ----
__device__ __align__(16) float        g_S[NBLK * 3072];   // [blk][p=3t+c]
__device__ __align__(16) unsigned int g_C[NBLK * 768];    // [blk][3*(t>>2)+c], byte=t&3
__device__ __align__(16) float        g_pS[3072];
__device__ __align__(16) int          g_pN[3072];
__device__ unsigned int g_rcnt;

// ======================= special functions =======================
__device__ __forceinline__ float stirl_lg(float y) {
    float r  = __fdividef(1.0f, y);
    float L  = __logf(y);
    float r2 = r * r;
    return fmaf(y - 0.5f, L,
                fmaf(r, fmaf(r2, -2.7777778e-3f, 8.3333333e-2f), 0.91893853f - y));
}

__device__ __forceinline__ void stirl_both(float y, float& lg, float& ps) {
    float r  = __fdividef(1.0f, y);
    float L  = __logf(y);
    float r2 = r * r;
    lg = fmaf(y - 0.5f, L,
              fmaf(r, fmaf(r2, -2.7777778e-3f, 8.3333333e-2f), 0.91893853f - y));
    ps = fmaf(-r2, fmaf(-r2, 8.3333333e-3f, 8.3333333e-2f), fmaf(-0.5f, r, L));
}

__device__ __forceinline__ float elem_kl(float l0, float l1, float tw, float tcv) {
    float pw  = __fdividef(1.0f, 1.0f + __expf(-l0));
    float pcs = __fdividef(1.0f, 1.0f + __expf(-l1));
    float pc  = fmaf(pcs, 1023.0f, 5.0f);

    float sp = tcv + 2.0f;
    float sq = pc + 2.0f;
    float ta = fmaf(tcv, tw, 1.0f);
    float tb = sp - ta;
    float pa = fmaf(pc, pw, 1.0f);
    float pb = sq - pa;

    float uta = ta * (ta + 3.0f), Pta = uta * (uta + 2.0f);
    float utb = tb * (tb + 3.0f), Ptb = utb * (utb + 2.0f);
    float upa = pa * (pa + 3.0f), Ppa = upa * (upa + 2.0f);
    float upb = pb * (pb + 3.0f), Ppb = upb * (upb + 2.0f);

    float lgta, psta; stirl_both(ta + 4.0f, lgta, psta);
    float lgtb, pstb; stirl_both(tb + 4.0f, lgtb, pstb);
    float lgsp, pssp; stirl_both(sp,        lgsp, pssp);
    float lgpa = stirl_lg(pa + 4.0f);
    float lgpb = stirl_lg(pb + 4.0f);
    float lgsq = stirl_lg(sq);

    float da = ta - pa, db = tb - pb;
    float Aa  = fmaf(2.0f, uta, 2.0f) * fmaf(2.0f, ta, 3.0f);
    float Ab  = fmaf(2.0f, utb, 2.0f) * fmaf(2.0f, tb, 3.0f);
    float Ptt = Pta * Ptb;
    float corr = __fdividef(fmaf(da * Aa, Ptb, db * Ab * Pta), Ptt);

    float logdiff = __logf(Ptt) - __logf(Ppa * Ppb);

    return (lgpa + lgpb + lgsp) - (lgta + lgtb + lgsq) + logdiff
         + da * psta + db * pstb + (sq - sp) * pssp - corr;
}

// ======================= kernel 1: main KL pass (R3 schedule) =======================
__global__ void __launch_bounds__(256)
main_kernel(const float* __restrict__ logits, const float* __restrict__ tgt) {
    const int tid = threadIdx.x;
    const float4* tg4 = reinterpret_cast<const float4*>(tgt);
    const float4* lg4 = reinterpret_cast<const float4*>(logits);

    float s[4][3];
#pragma unroll
    for (int j = 0; j < 4; j++) { s[j][0] = 0.0f; s[j][1] = 0.0f; s[j][2] = 0.0f; }
    unsigned int cn0 = 0, cn1 = 0, cn2 = 0;

#pragma unroll 1
    for (int g = blockIdx.x * 256 + tid; g < TOTAL4; g += NBLK * 256) {
        float4 a = tg4[g * 3 + 0];
        float4 b = tg4[g * 3 + 1];
        float4 c = tg4[g * 3 + 2];
        float4 d = lg4[g * 2 + 0];
        float4 e = lg4[g * 2 + 1];
        float tv[12] = {a.x, a.y, a.z, a.w, b.x, b.y, b.z, b.w, c.x, c.y, c.z, c.w};
        float lv[8]  = {d.x, d.y, d.z, d.w, e.x, e.y, e.z, e.w};
#pragma unroll
        for (int j = 0; j < 4; j++) {
            float x0 = tv[3 * j], x1 = tv[3 * j + 1], x2 = tv[3 * j + 2];
            bool  m  = (x2 > NEGBIG);
            float tw = m ? x0 : 0.5f;
            float tc = m ? x1 : 5.0f;
            int   dx = m ? (int)x2 : -1;
            float kl = elem_kl(lv[2 * j], lv[2 * j + 1], tw, tc);
            s[j][0] += (dx == 0) ? kl : 0.0f;
            s[j][1] += (dx == 1) ? kl : 0.0f;
            s[j][2] += (dx == 2) ? kl : 0.0f;
            cn0 += (dx == 0) ? (1u << (8 * j)) : 0u;
            cn1 += (dx == 1) ? (1u << (8 * j)) : 0u;
            cn2 += (dx == 2) ? (1u << (8 * j)) : 0u;
        }
    }

    // coalesced slab write: [blk][12*tid + 3j + c] == [blk][3t + c]
    float4* so = reinterpret_cast<float4*>(&g_S[blockIdx.x * 3072 + 12 * tid]);
    so[0] = make_float4(s[0][0], s[0][1], s[0][2], s[1][0]);
    so[1] = make_float4(s[1][1], s[1][2], s[2][0], s[2][1]);
    so[2] = make_float4(s[2][2], s[3][0], s[3][1], s[3][2]);
    unsigned int* co = &g_C[blockIdx.x * 768 + 3 * tid];
    co[0] = cn0; co[1] = cn1; co[2] = cn2;
}

// ======================= kernel 2: coalesced reduce + finalize =======================
// Blocks 0..95: S. Block owns 32 consecutive p; warp w sums blocks [w*74,(w+1)*74).
// Blocks 96..119: packed counts, same pattern over the 768 count words.
__global__ void __launch_bounds__(256)
reduce_kernel(float* __restrict__ out) {
    const int tid = threadIdx.x;
    const int w = tid >> 5, l = tid & 31;
    __shared__ float sS[8][32];
    __shared__ int   sN[8][32][4];

    if (blockIdx.x < 96) {
        const int p  = blockIdx.x * 32 + l;
        const int b0 = w * PER;
        float acc = 0.0f;
#pragma unroll 8
        for (int b = b0; b < b0 + PER; b++)
            acc += g_S[b * 3072 + p];                    // 128B/warp, coalesced
        sS[w][l] = acc;
        __syncthreads();
        if (w == 0) {
            float s = 0.0f;
#pragma unroll
            for (int i = 0; i < 8; i++) s += sS[i][l];   // fixed order
            g_pS[p] = s;
        }
    } else {
        const int wi = (blockIdx.x - 96) * 32 + l;       // count word 0..767
        const int b0 = w * PER;
        int n[4] = {0, 0, 0, 0};
#pragma unroll 1
        for (int c0 = 0; c0 < PER; c0 += 25) {           // 25*7 = 175 <= 255: no carry
            unsigned int acc = 0;
            int lim = (c0 + 25 < PER) ? (c0 + 25) : PER;
#pragma unroll 8
            for (int b = b0 + c0; b < b0 + lim; b++)
                acc += g_C[b * 768 + wi];                // 128B/warp, coalesced
            n[0] += (int)(acc & 0xFFu);
            n[1] += (int)((acc >> 8) & 0xFFu);
            n[2] += (int)((acc >> 16) & 0xFFu);
            n[3] += (int)(acc >> 24);
        }
#pragma unroll
        for (int j = 0; j < 4; j++) sN[w][l][j] = n[j];
        __syncthreads();
        if (w == 0) {
            int t4 = wi / 3, c = wi - 3 * t4;            // byte j -> t = 4*t4+j
#pragma unroll
            for (int j = 0; j < 4; j++) {
                int s = 0;
#pragma unroll
                for (int i = 0; i < 8; i++) s += sN[i][l][j];
                g_pN[12 * t4 + 3 * j + c] = s;
            }
        }
    }

    __threadfence();
    __syncthreads();
    __shared__ bool amLast;
    if (tid == 0)
        amLast = (atomicAdd(&g_rcnt, 1u) == (unsigned)(RBLKS - 1));
    __syncthreads();
    if (!amLast) return;
    __threadfence();

    // fold: thread owns t = 4*tid+j; 12 S + 12 N contiguous reads
    const float4* ps4 = reinterpret_cast<const float4*>(&g_pS[12 * tid]);
    const int4*   pn4 = reinterpret_cast<const int4*>(&g_pN[12 * tid]);
    float acc = 0.0f;
#pragma unroll
    for (int k = 0; k < 3; k++) {
        float4 S = ps4[k];
        int4   N = pn4[k];
        acc += (N.x > 0) ? __fdividef(S.x, 3.0f * (float)N.x) : 0.0f;
        acc += (N.y > 0) ? __fdividef(S.y, 3.0f * (float)N.y) : 0.0f;
        acc += (N.z > 0) ? __fdividef(S.z, 3.0f * (float)N.z) : 0.0f;
        acc += (N.w > 0) ? __fdividef(S.w, 3.0f * (float)N.w) : 0.0f;
    }

#pragma unroll
    for (int off = 16; off > 0; off >>= 1)
        acc += __shfl_xor_sync(0xffffffffu, acc, off);
    __shared__ float ws[8];
    if ((tid & 31) == 0) ws[tid >> 5] = acc;
    __syncthreads();
    if (tid == 0) {
        float tot = 0.0f;
#pragma unroll
        for (int i = 0; i < 8; i++) tot += ws[i];
        out[0] = tot * (1.0f / (float)TT);
        g_rcnt = 0;                                      // reset for next replay
    }
}

// ======================= launch =======================
extern "C" void kernel_launch(void* const* d_in, const int* in_sizes, int n_in,
                              void* d_out, int out_size) {
    const float* logits;
    const float* targets;
    if (in_sizes[0] == BB * TT * 2) {
        logits  = (const float*)d_in[0];
        targets = (const float*)d_in[1];
    } else {
        logits  = (const float*)d_in[1];
        targets = (const float*)d_in[0];
    }
    float* out = (float*)d_out;

    main_kernel<<<NBLK, 256>>>(logits, targets);
    reduce_kernel<<<RBLKS, 256>>>(out);
}

// round 6
// speedup vs baseline: 2.9037x; 1.1349x over previous
#include <cuda_runtime.h>
#include <cuda_bf16.h>

#define TT 1024
#define BB 4096
#define TOTAL4 (BB * TT / 4)        // 1048576 float4-groups
#define NBLK 148                    // 1 CTA of 1024 threads per SM
#define RBLKS 120                   // 96 S-blocks + 24 count-blocks
#define NEGBIG (-1.0e30f)

// ---- device scratch (static; counter self-resets each launch) ----
__device__ __align__(16) float        g_S[NBLK * 3072];   // [blk][p=3t+c]
__device__ __align__(16) unsigned int g_C[NBLK * 768];    // [blk][3*(t>>2)+c], byte=t&3
__device__ __align__(16) float        g_pS[3072];
__device__ __align__(16) int          g_pN[3072];
__device__ unsigned int g_rcnt;

// ======================= special functions =======================
__device__ __forceinline__ float stirl_lg(float y) {
    float r  = __fdividef(1.0f, y);
    float L  = __logf(y);
    float r2 = r * r;
    return fmaf(y - 0.5f, L,
                fmaf(r, fmaf(r2, -2.7777778e-3f, 8.3333333e-2f), 0.91893853f - y));
}

__device__ __forceinline__ void stirl_both(float y, float& lg, float& ps) {
    float r  = __fdividef(1.0f, y);
    float L  = __logf(y);
    float r2 = r * r;
    lg = fmaf(y - 0.5f, L,
              fmaf(r, fmaf(r2, -2.7777778e-3f, 8.3333333e-2f), 0.91893853f - y));
    ps = fmaf(-r2, fmaf(-r2, 8.3333333e-3f, 8.3333333e-2f), fmaf(-0.5f, r, L));
}

__device__ __forceinline__ float elem_kl(float l0, float l1, float tw, float tcv) {
    float pw  = __fdividef(1.0f, 1.0f + __expf(-l0));
    float pcs = __fdividef(1.0f, 1.0f + __expf(-l1));
    float pc  = fmaf(pcs, 1023.0f, 5.0f);

    float sp = tcv + 2.0f;
    float sq = pc + 2.0f;
    float ta = fmaf(tcv, tw, 1.0f);
    float tb = sp - ta;
    float pa = fmaf(pc, pw, 1.0f);
    float pb = sq - pa;

    float uta = ta * (ta + 3.0f), Pta = uta * (uta + 2.0f);
    float utb = tb * (tb + 3.0f), Ptb = utb * (utb + 2.0f);
    float upa = pa * (pa + 3.0f), Ppa = upa * (upa + 2.0f);
    float upb = pb * (pb + 3.0f), Ppb = upb * (upb + 2.0f);

    float lgta, psta; stirl_both(ta + 4.0f, lgta, psta);
    float lgtb, pstb; stirl_both(tb + 4.0f, lgtb, pstb);
    float lgsp, pssp; stirl_both(sp,        lgsp, pssp);
    float lgpa = stirl_lg(pa + 4.0f);
    float lgpb = stirl_lg(pb + 4.0f);
    float lgsq = stirl_lg(sq);

    float da = ta - pa, db = tb - pb;
    float Aa  = fmaf(2.0f, uta, 2.0f) * fmaf(2.0f, ta, 3.0f);
    float Ab  = fmaf(2.0f, utb, 2.0f) * fmaf(2.0f, tb, 3.0f);
    float Ptt = Pta * Ptb;
    float corr = __fdividef(fmaf(da * Aa, Ptb, db * Ab * Pta), Ptt);

    float logdiff = __logf(Ptt) - __logf(Ppa * Ppb);

    return (lgpa + lgpb + lgsp) - (lgta + lgtb + lgsq) + logdiff
         + da * psta + db * pstb + (sq - sp) * pssp - corr;
}

// ======================= kernel 1: main KL pass =======================
// 148 blocks x 1024 threads. Thread owns t = 4*(tid&255)+j; the 4 thread-
// quarters share t-sets and fold in smem before one small coalesced slab write.
__global__ void __launch_bounds__(1024)
main_kernel(const float* __restrict__ logits, const float* __restrict__ tgt) {
    const int tid = threadIdx.x;
    const int q = tid >> 8, r = tid & 255;
    const float4* tg4 = reinterpret_cast<const float4*>(tgt);
    const float4* lg4 = reinterpret_cast<const float4*>(logits);

    float s[4][3];
#pragma unroll
    for (int j = 0; j < 4; j++) { s[j][0] = 0.0f; s[j][1] = 0.0f; s[j][2] = 0.0f; }
    unsigned int cn[3] = {0u, 0u, 0u};

#pragma unroll 1
    for (int g = blockIdx.x * 1024 + tid; g < TOTAL4; g += NBLK * 1024) {
        float4 a = tg4[g * 3 + 0];
        float4 b = tg4[g * 3 + 1];
        float4 c = tg4[g * 3 + 2];
        float4 d = lg4[g * 2 + 0];
        float4 e = lg4[g * 2 + 1];
        float tv[12] = {a.x, a.y, a.z, a.w, b.x, b.y, b.z, b.w, c.x, c.y, c.z, c.w};
        float lv[8]  = {d.x, d.y, d.z, d.w, e.x, e.y, e.z, e.w};
#pragma unroll
        for (int j = 0; j < 4; j++) {
            float x0 = tv[3 * j], x1 = tv[3 * j + 1], x2 = tv[3 * j + 2];
            bool  m  = (x2 > NEGBIG);
            float tw = m ? x0 : 0.5f;
            float tc = m ? x1 : 5.0f;
            int   dx = m ? (int)x2 : -1;
            float kl = elem_kl(lv[2 * j], lv[2 * j + 1], tw, tc);
            s[j][0] += (dx == 0) ? kl : 0.0f;
            s[j][1] += (dx == 1) ? kl : 0.0f;
            s[j][2] += (dx == 2) ? kl : 0.0f;
            cn[0] += (dx == 0) ? (1u << (8 * j)) : 0u;
            cn[1] += (dx == 1) ? (1u << (8 * j)) : 0u;
            cn[2] += (dx == 2) ? (1u << (8 * j)) : 0u;
        }
    }

    // 4-phase fixed-order quarter fold in smem
    __shared__ float        sh[3072];
    __shared__ unsigned int shc[768];
    if (q == 0) {
#pragma unroll
        for (int j = 0; j < 4; j++)
#pragma unroll
            for (int c = 0; c < 3; c++) sh[12 * r + 3 * j + c] = s[j][c];
#pragma unroll
        for (int c = 0; c < 3; c++) shc[3 * r + c] = cn[c];
    }
    __syncthreads();
#pragma unroll
    for (int qq = 1; qq < 4; qq++) {
        if (q == qq) {
#pragma unroll
            for (int j = 0; j < 4; j++)
#pragma unroll
                for (int c = 0; c < 3; c++) sh[12 * r + 3 * j + c] += s[j][c];
#pragma unroll
            for (int c = 0; c < 3; c++) shc[3 * r + c] += cn[c];
        }
        __syncthreads();
    }

    if (q == 0) {
        const float4* shv = reinterpret_cast<const float4*>(&sh[12 * r]);
        float4* so = reinterpret_cast<float4*>(&g_S[blockIdx.x * 3072 + 12 * r]);
        so[0] = shv[0]; so[1] = shv[1]; so[2] = shv[2];
        unsigned int* co = &g_C[blockIdx.x * 768 + 3 * r];
        co[0] = shc[3 * r]; co[1] = shc[3 * r + 1]; co[2] = shc[3 * r + 2];
    }
}

// ======================= kernel 2: reduce + finalize =======================
// Blocks 0..95: S (p = blk*32+lane; warp w sums b = w, w+8, ...).
// Blocks 96..119: packed counts (chunked unpack, byte <= 28*9=252 per chunk).
__global__ void __launch_bounds__(256)
reduce_kernel(float* __restrict__ out) {
    const int tid = threadIdx.x;
    const int w = tid >> 5, l = tid & 31;
    __shared__ float sS[8][32];
    __shared__ int   sN[8][32][4];

    if (blockIdx.x < 96) {
        const int p = blockIdx.x * 32 + l;
        float acc = 0.0f;
#pragma unroll
        for (int b = w; b < NBLK; b += 8)
            acc += g_S[b * 3072 + p];                    // coalesced per warp
        sS[w][l] = acc;
        __syncthreads();
        if (w == 0) {
            float ssum = 0.0f;
#pragma unroll
            for (int i = 0; i < 8; i++) ssum += sS[i][l];
            g_pS[p] = ssum;
        }
    } else {
        const int wi = (blockIdx.x - 96) * 32 + l;       // count word 0..767
        int n[4] = {0, 0, 0, 0};
        int b = w;
#pragma unroll
        for (int chunk = 0; chunk < 3; chunk++) {        // 9+9+9 >= 19 iters
            unsigned int acc = 0;
#pragma unroll
            for (int i = 0; i < 9; i++) {
                if (b < NBLK) { acc += g_C[b * 768 + wi]; b += 8; }
            }
            n[0] += (int)(acc & 0xFFu);
            n[1] += (int)((acc >> 8) & 0xFFu);
            n[2] += (int)((acc >> 16) & 0xFFu);
            n[3] += (int)(acc >> 24);
        }
#pragma unroll
        for (int j = 0; j < 4; j++) sN[w][l][j] = n[j];
        __syncthreads();
        if (w == 0) {
            int t4 = wi / 3, c = wi - 3 * t4;            // byte j -> t = 4*t4+j
#pragma unroll
            for (int j = 0; j < 4; j++) {
                int nsum = 0;
#pragma unroll
                for (int i = 0; i < 8; i++) nsum += sN[i][l][j];
                g_pN[12 * t4 + 3 * j + c] = nsum;
            }
        }
    }

    __threadfence();
    __syncthreads();
    __shared__ bool amLast;
    if (tid == 0)
        amLast = (atomicAdd(&g_rcnt, 1u) == (unsigned)(RBLKS - 1));
    __syncthreads();
    if (!amLast) return;
    __threadfence();

    // fold: thread owns t = 4*tid+j; 12 S + 12 N contiguous reads
    const float4* ps4 = reinterpret_cast<const float4*>(&g_pS[12 * tid]);
    const int4*   pn4 = reinterpret_cast<const int4*>(&g_pN[12 * tid]);
    float acc = 0.0f;
#pragma unroll
    for (int k = 0; k < 3; k++) {
        float4 S = ps4[k];
        int4   N = pn4[k];
        acc += (N.x > 0) ? __fdividef(S.x, 3.0f * (float)N.x) : 0.0f;
        acc += (N.y > 0) ? __fdividef(S.y, 3.0f * (float)N.y) : 0.0f;
        acc += (N.z > 0) ? __fdividef(S.z, 3.0f * (float)N.z) : 0.0f;
        acc += (N.w > 0) ? __fdividef(S.w, 3.0f * (float)N.w) : 0.0f;
    }

#pragma unroll
    for (int off = 16; off > 0; off >>= 1)
        acc += __shfl_xor_sync(0xffffffffu, acc, off);
    __shared__ float ws[8];
    if ((tid & 31) == 0) ws[tid >> 5] = acc;
    __syncthreads();
    if (tid == 0) {
        float tot = 0.0f;
#pragma unroll
        for (int i = 0; i < 8; i++) tot += ws[i];
        out[0] = tot * (1.0f / (float)TT);
        g_rcnt = 0;                                      // reset for next replay
    }
}

// ======================= launch =======================
extern "C" void kernel_launch(void* const* d_in, const int* in_sizes, int n_in,
                              void* d_out, int out_size) {
    const float* logits;
    const float* targets;
    if (in_sizes[0] == BB * TT * 2) {
        logits  = (const float*)d_in[0];
        targets = (const float*)d_in[1];
    } else {
        logits  = (const float*)d_in[1];
        targets = (const float*)d_in[0];
    }
    float* out = (float*)d_out;

    main_kernel<<<NBLK, 1024>>>(logits, targets);
    reduce_kernel<<<RBLKS, 256>>>(out);
}